// round 1
// baseline (speedup 1.0000x reference)
#include <cuda_runtime.h>
#include <cstdint>

#define T_ 2048
#define B_ 32
#define V_ 128
#define L_ 256
#define S_ 513
#define NEG (-1e30f)
#define NT_ 544   // 17 warps covers 513 states

// Scratch (no allocations allowed)
__device__ float g_denom[T_ * B_];
__device__ float g_nll[B_];

// ---------------------------------------------------------------------------
// Kernel 1: per-(t,b) log-sum-exp denominator. One warp per 128-float row.
// ---------------------------------------------------------------------------
__global__ void k_denom(const float* __restrict__ acts) {
    int warp = (blockIdx.x * blockDim.x + threadIdx.x) >> 5;
    int lane = threadIdx.x & 31;
    if (warp >= T_ * B_) return;
    float4 v = reinterpret_cast<const float4*>(acts)[warp * 32 + lane];
    float m = fmaxf(fmaxf(v.x, v.y), fmaxf(v.z, v.w));
#pragma unroll
    for (int o = 16; o; o >>= 1) m = fmaxf(m, __shfl_xor_sync(0xffffffffu, m, o));
    float s = __expf(v.x - m) + __expf(v.y - m) + __expf(v.z - m) + __expf(v.w - m);
#pragma unroll
    for (int o = 16; o; o >>= 1) s += __shfl_xor_sync(0xffffffffu, s, o);
    if (lane == 0) g_denom[warp] = m + __logf(s);
}

// ---------------------------------------------------------------------------
// Kernel 2: alpha recursion. One CTA per batch sample, thread s owns state s.
// Registers hold alpha; warp-boundary values (2 per warp) go through a
// double-buffered shared array; activation row t+1 prefetched via cp.async.
// One __syncthreads per time step.
// ---------------------------------------------------------------------------
__global__ __launch_bounds__(NT_, 1) void k_alpha(
    const float* __restrict__ acts, const int* __restrict__ labels,
    const int* __restrict__ act_lens, const int* __restrict__ label_lens)
{
    __shared__ float rowbuf[2][V_];
    __shared__ float bb[2][34];      // [buf][warp*2 + {lane30,lane31}]
    __shared__ float sEnd[2];

    const int b    = blockIdx.x;
    const int tid  = threadIdx.x;
    const int lane = tid & 31;
    const int w    = tid >> 5;
    const int s    = tid;

    const int labLen = label_lens[b];
    const int actLen = act_lens[b];
    const int Sv     = 2 * labLen + 1;
    const bool active = (s < S_);
    const bool valid  = active && (s < Sv);

    int  extv = 0;
    bool skip = false;
    if (active && (s & 1)) {
        extv = labels[b * L_ + (s >> 1)];
        if (s >= 3) skip = (extv != labels[b * L_ + (s >> 1) - 1]);
    }
    const int e1 = 2 * labLen;
    const int e2 = 2 * labLen - 1;

    const float* actsB = acts + (size_t)b * V_;

    // --- prefetch row 0 ---
    if (tid < 32) {
        uint32_t dst = (uint32_t)__cvta_generic_to_shared(&rowbuf[0][lane * 4]);
        const float4* src = reinterpret_cast<const float4*>(actsB) + lane;
        asm volatile("cp.async.cg.shared.global [%0], [%1], 16;\n" ::"r"(dst), "l"(src) : "memory");
        asm volatile("cp.async.commit_group;\n" ::: "memory");
    }
    asm volatile("cp.async.wait_group 0;\n" ::: "memory");
    __syncthreads();

    // --- alpha at t = 0 ---
    float d0 = g_denom[b];
    float alpha = (valid && s < 2) ? (rowbuf[0][extv] - d0) : NEG;
    if (lane == 30) bb[0][w * 2]     = alpha;
    if (lane == 31) bb[0][w * 2 + 1] = alpha;
    if (actLen == 1) {
        if (s == e1) sEnd[0] = alpha;
        if (s == e2) sEnd[1] = alpha;
    }
    // prefetch row 1
    if (tid < 32) {
        uint32_t dst = (uint32_t)__cvta_generic_to_shared(&rowbuf[1][lane * 4]);
        const float4* src = reinterpret_cast<const float4*>(actsB + (size_t)1 * B_ * V_) + lane;
        asm volatile("cp.async.cg.shared.global [%0], [%1], 16;\n" ::"r"(dst), "l"(src) : "memory");
        asm volatile("cp.async.commit_group;\n" ::: "memory");
    }
    asm volatile("cp.async.wait_group 0;\n" ::: "memory");
    __syncthreads();

    // --- main recursion ---
    for (int t = 1; t < T_; ++t) {
        const int buf = t & 1, pbuf = buf ^ 1;

        float dt = g_denom[t * B_ + b];
        float lp = rowbuf[buf][extv] - dt;

        float a1 = __shfl_up_sync(0xffffffffu, alpha, 1);
        float a2 = __shfl_up_sync(0xffffffffu, alpha, 2);
        if (lane == 0) {
            a1 = (w > 0) ? bb[pbuf][(w - 1) * 2 + 1] : NEG;
            a2 = (w > 0) ? bb[pbuf][(w - 1) * 2]     : NEG;
        } else if (lane == 1) {
            a2 = (w > 0) ? bb[pbuf][(w - 1) * 2 + 1] : NEG;
        }

        float a2s = skip ? a2 : NEG;
        float m   = fmaxf(fmaxf(alpha, a1), a2s);
        float sum = __expf(alpha - m) + __expf(a1 - m);
        if (skip) sum += __expf(a2 - m);
        alpha = valid ? (m + __logf(sum) + lp) : NEG;

        if (lane == 30) bb[buf][w * 2]     = alpha;
        if (lane == 31) bb[buf][w * 2 + 1] = alpha;
        if (t == actLen - 1) {
            if (s == e1) sEnd[0] = alpha;
            if (s == e2) sEnd[1] = alpha;
        }

        if (tid < 32 && (t + 1) < T_) {
            uint32_t dst = (uint32_t)__cvta_generic_to_shared(&rowbuf[pbuf][lane * 4]);
            const float4* src = reinterpret_cast<const float4*>(actsB + (size_t)(t + 1) * B_ * V_) + lane;
            asm volatile("cp.async.cg.shared.global [%0], [%1], 16;\n" ::"r"(dst), "l"(src) : "memory");
            asm volatile("cp.async.commit_group;\n" ::: "memory");
        }
        asm volatile("cp.async.wait_group 0;\n" ::: "memory");
        __syncthreads();
    }

    if (tid == 0) {
        float x = sEnd[0], y = sEnd[1];
        float mm = fmaxf(x, y);
        g_nll[b] = -(mm + __logf(__expf(x - mm) + __expf(y - mm)));
    }
}

// ---------------------------------------------------------------------------
// Kernel 3: mean over batch -> d_out[0]
// ---------------------------------------------------------------------------
__global__ void k_final(float* __restrict__ out) {
    float v = (threadIdx.x < B_) ? g_nll[threadIdx.x] : 0.f;
#pragma unroll
    for (int o = 16; o; o >>= 1) v += __shfl_xor_sync(0xffffffffu, v, o);
    if (threadIdx.x == 0) out[0] = v * (1.0f / B_);
}

extern "C" void kernel_launch(void* const* d_in, const int* in_sizes, int n_in,
                              void* d_out, int out_size)
{
    const float* acts       = (const float*)d_in[0];
    const int*   labels     = (const int*)d_in[1];
    const int*   act_lens   = (const int*)d_in[2];
    const int*   label_lens = (const int*)d_in[3];

    // 65536 rows, one warp each, 8 warps / block
    k_denom<<<(T_ * B_) / 8, 256>>>(acts);
    k_alpha<<<B_, NT_>>>(acts, labels, act_lens, label_lens);
    k_final<<<1, 32>>>((float*)d_out);
}

// round 2
// speedup vs baseline: 1.0034x; 1.0034x over previous
#include <cuda_runtime.h>
#include <cstdint>

#define T_ 2048
#define B_ 32
#define V_ 128
#define L_ 256
#define S_ 513
#define NEG (-1e30f)
#define NT_ 544   // 17 warps covers 513 states

// Scratch (no allocations allowed)
__device__ float g_denom[T_ * B_];
__device__ float g_nll[B_];

// ---------------------------------------------------------------------------
// Kernel 1: per-(t,b) log-sum-exp denominator. One warp per 128-float row.
// ---------------------------------------------------------------------------
__global__ void k_denom(const float* __restrict__ acts) {
    int warp = (blockIdx.x * blockDim.x + threadIdx.x) >> 5;
    int lane = threadIdx.x & 31;
    if (warp >= T_ * B_) return;
    float4 v = reinterpret_cast<const float4*>(acts)[warp * 32 + lane];
    float m = fmaxf(fmaxf(v.x, v.y), fmaxf(v.z, v.w));
#pragma unroll
    for (int o = 16; o; o >>= 1) m = fmaxf(m, __shfl_xor_sync(0xffffffffu, m, o));
    float s = __expf(v.x - m) + __expf(v.y - m) + __expf(v.z - m) + __expf(v.w - m);
#pragma unroll
    for (int o = 16; o; o >>= 1) s += __shfl_xor_sync(0xffffffffu, s, o);
    if (lane == 0) g_denom[warp] = m + __logf(s);
}

// ---------------------------------------------------------------------------
// Kernel 2: alpha recursion. One CTA per batch sample, thread s owns state s.
// Registers hold alpha; warp-boundary values (2 per warp) go through a
// double-buffered shared array; activation row t+1 prefetched via cp.async.
// One __syncthreads per time step.
// ---------------------------------------------------------------------------
__global__ __launch_bounds__(NT_, 1) void k_alpha(
    const float* __restrict__ acts, const int* __restrict__ labels,
    const int* __restrict__ act_lens, const int* __restrict__ label_lens)
{
    __shared__ float rowbuf[2][V_];
    __shared__ float bb[2][34];      // [buf][warp*2 + {lane30,lane31}]
    __shared__ float sEnd[2];

    const int b    = blockIdx.x;
    const int tid  = threadIdx.x;
    const int lane = tid & 31;
    const int w    = tid >> 5;
    const int s    = tid;

    const int labLen = label_lens[b];
    const int actLen = act_lens[b];
    const int Sv     = 2 * labLen + 1;
    const bool active = (s < S_);
    const bool valid  = active && (s < Sv);

    int  extv = 0;
    bool skip = false;
    if (active && (s & 1)) {
        extv = labels[b * L_ + (s >> 1)];
        if (s >= 3) skip = (extv != labels[b * L_ + (s >> 1) - 1]);
    }
    const int e1 = 2 * labLen;
    const int e2 = 2 * labLen - 1;

    const float* actsB = acts + (size_t)b * V_;

    // --- prefetch row 0 ---
    if (tid < 32) {
        uint32_t dst = (uint32_t)__cvta_generic_to_shared(&rowbuf[0][lane * 4]);
        const float4* src = reinterpret_cast<const float4*>(actsB) + lane;
        asm volatile("cp.async.cg.shared.global [%0], [%1], 16;\n" ::"r"(dst), "l"(src) : "memory");
        asm volatile("cp.async.commit_group;\n" ::: "memory");
    }
    asm volatile("cp.async.wait_group 0;\n" ::: "memory");
    __syncthreads();

    // --- alpha at t = 0 ---
    float d0 = g_denom[b];
    float alpha = (valid && s < 2) ? (rowbuf[0][extv] - d0) : NEG;
    if (lane == 30) bb[0][w * 2]     = alpha;
    if (lane == 31) bb[0][w * 2 + 1] = alpha;
    if (actLen == 1) {
        if (s == e1) sEnd[0] = alpha;
        if (s == e2) sEnd[1] = alpha;
    }
    // prefetch row 1
    if (tid < 32) {
        uint32_t dst = (uint32_t)__cvta_generic_to_shared(&rowbuf[1][lane * 4]);
        const float4* src = reinterpret_cast<const float4*>(actsB + (size_t)1 * B_ * V_) + lane;
        asm volatile("cp.async.cg.shared.global [%0], [%1], 16;\n" ::"r"(dst), "l"(src) : "memory");
        asm volatile("cp.async.commit_group;\n" ::: "memory");
    }
    asm volatile("cp.async.wait_group 0;\n" ::: "memory");
    __syncthreads();

    // --- main recursion ---
    for (int t = 1; t < T_; ++t) {
        const int buf = t & 1, pbuf = buf ^ 1;

        float dt = g_denom[t * B_ + b];
        float lp = rowbuf[buf][extv] - dt;

        float a1 = __shfl_up_sync(0xffffffffu, alpha, 1);
        float a2 = __shfl_up_sync(0xffffffffu, alpha, 2);
        if (lane == 0) {
            a1 = (w > 0) ? bb[pbuf][(w - 1) * 2 + 1] : NEG;
            a2 = (w > 0) ? bb[pbuf][(w - 1) * 2]     : NEG;
        } else if (lane == 1) {
            a2 = (w > 0) ? bb[pbuf][(w - 1) * 2 + 1] : NEG;
        }

        float a2s = skip ? a2 : NEG;
        float m   = fmaxf(fmaxf(alpha, a1), a2s);
        float sum = __expf(alpha - m) + __expf(a1 - m);
        if (skip) sum += __expf(a2 - m);
        alpha = valid ? (m + __logf(sum) + lp) : NEG;

        if (lane == 30) bb[buf][w * 2]     = alpha;
        if (lane == 31) bb[buf][w * 2 + 1] = alpha;
        if (t == actLen - 1) {
            if (s == e1) sEnd[0] = alpha;
            if (s == e2) sEnd[1] = alpha;
        }

        if (tid < 32 && (t + 1) < T_) {
            uint32_t dst = (uint32_t)__cvta_generic_to_shared(&rowbuf[pbuf][lane * 4]);
            const float4* src = reinterpret_cast<const float4*>(actsB + (size_t)(t + 1) * B_ * V_) + lane;
            asm volatile("cp.async.cg.shared.global [%0], [%1], 16;\n" ::"r"(dst), "l"(src) : "memory");
            asm volatile("cp.async.commit_group;\n" ::: "memory");
        }
        asm volatile("cp.async.wait_group 0;\n" ::: "memory");
        __syncthreads();
    }

    if (tid == 0) {
        float x = sEnd[0], y = sEnd[1];
        float mm = fmaxf(x, y);
        g_nll[b] = -(mm + __logf(__expf(x - mm) + __expf(y - mm)));
    }
}

// ---------------------------------------------------------------------------
// Kernel 3: mean over batch -> d_out[0]
// ---------------------------------------------------------------------------
__global__ void k_final(float* __restrict__ out) {
    float v = (threadIdx.x < B_) ? g_nll[threadIdx.x] : 0.f;
#pragma unroll
    for (int o = 16; o; o >>= 1) v += __shfl_xor_sync(0xffffffffu, v, o);
    if (threadIdx.x == 0) out[0] = v * (1.0f / B_);
}

extern "C" void kernel_launch(void* const* d_in, const int* in_sizes, int n_in,
                              void* d_out, int out_size)
{
    const float* acts       = (const float*)d_in[0];
    const int*   labels     = (const int*)d_in[1];
    const int*   act_lens   = (const int*)d_in[2];
    const int*   label_lens = (const int*)d_in[3];

    // 65536 rows, one warp each, 8 warps / block
    k_denom<<<(T_ * B_) / 8, 256>>>(acts);
    k_alpha<<<B_, NT_>>>(acts, labels, act_lens, label_lens);
    k_final<<<1, 32>>>((float*)d_out);
}